// round 6
// baseline (speedup 1.0000x reference)
#include <cuda_runtime.h>
#include <cuda_bf16.h>
#include <cstdint>

#define NROWS 16384
#define FIN 64
#define FOUT 64
#define NP 80             // g_B row: 0..63 = feat@W2^T, 64 = ones, 65..79 = 0
#define NC 72             // stored C cols
#define MT 128            // M rows per CTA
#define KC 32             // K per chunk
#define KHALF (NROWS / 2)
#define NCHUNK (KHALF / KC)     // 256
#define SA 40             // A smem stride (bf16), conflict-free LDSM
#define SB 88             // B smem stride (bf16), conflict-free LDSM
#define BSTG 4
#define B_STG_ELEM (KC * SB)    // 2816 bf16 = 5632 B
#define PREP_SMEM ((64 * 65 + 128 * 64) * 4)

__device__ __align__(256) __nv_bfloat16 g_B[NROWS * NP];
__device__ __align__(256) float g_F1[NROWS * FOUT];
__device__ __align__(256) float g_Cp[2][NROWS * NC];

__device__ __forceinline__ uint32_t smem_u32(const void* p) {
  uint32_t a;
  asm("{ .reg .u64 t; cvta.to.shared.u64 t, %1; cvt.u32.u64 %0, t; }" : "=r"(a) : "l"(p));
  return a;
}
__device__ __forceinline__ void cp16(uint32_t dst, const void* src) {
  asm volatile("cp.async.cg.shared.global [%0], [%1], 16;" :: "r"(dst), "l"(src));
}
#define CP_COMMIT() asm volatile("cp.async.commit_group;" ::: "memory")
#define CP_WAIT2()  asm volatile("cp.async.wait_group 2;" ::: "memory")
__device__ __forceinline__ void ldsm_x4(uint32_t* r, uint32_t a) {
  asm volatile("ldmatrix.sync.aligned.m8n8.x4.shared.b16 {%0,%1,%2,%3}, [%4];"
               : "=r"(r[0]), "=r"(r[1]), "=r"(r[2]), "=r"(r[3]) : "r"(a));
}
__device__ __forceinline__ void ldsm_x4t(uint32_t* r, uint32_t a) {
  asm volatile("ldmatrix.sync.aligned.m8n8.x4.trans.shared.b16 {%0,%1,%2,%3}, [%4];"
               : "=r"(r[0]), "=r"(r[1]), "=r"(r[2]), "=r"(r[3]) : "r"(a));
}
__device__ __forceinline__ void ldsm_x2t(uint32_t* r, uint32_t a) {
  asm volatile("ldmatrix.sync.aligned.m8n8.x2.trans.shared.b16 {%0,%1}, [%2];"
               : "=r"(r[0]), "=r"(r[1]) : "r"(a));
}
__device__ __forceinline__ void mma_bf16(float* c, const uint32_t* a, uint32_t b0, uint32_t b1) {
  asm volatile(
      "mma.sync.aligned.m16n8k16.row.col.f32.bf16.bf16.f32 "
      "{%0,%1,%2,%3}, {%4,%5,%6,%7}, {%8,%9}, {%0,%1,%2,%3};\n"
      : "+f"(c[0]), "+f"(c[1]), "+f"(c[2]), "+f"(c[3])
      : "r"(a[0]), "r"(a[1]), "r"(a[2]), "r"(a[3]), "r"(b0), "r"(b1));
}

// ---------------------------------------------------------------------------
__global__ void probe_kernel() {}   // placed so gemm is overall launch idx 3 (ncu slot)

// ---------------------------------------------------------------------------
// prep: g_F1 = feat@W1^T (f32); g_B[k][0..63] = feat@W2^T (bf16); 64=1; pad=0
// ---------------------------------------------------------------------------
__global__ __launch_bounds__(256, 2) void prep_kernel(const float* __restrict__ feat,
                                                      const float* __restrict__ W) {
  extern __shared__ float sm[];
  float* Fs = sm;             // [64][65]
  float* Ws = sm + 64 * 65;   // [128][64]
  const int tid = threadIdx.x;
  const int k0 = blockIdx.x * 64;

  for (int idx = tid; idx < 64 * 64; idx += 256) {
    int r = idx >> 6, j = idx & 63;
    Fs[r * 65 + j] = feat[(size_t)(k0 + r) * 64 + j];
  }
  for (int idx = tid; idx < 64 * 128; idx += 256) {
    int o = idx >> 7, j = idx & 127;
    Ws[((j < 64) ? o : 64 + o) * 64 + (j & 63)] = W[idx];
  }
  __syncthreads();

  const int r = tid & 63;
  const int q = tid >> 6;
  float acc[32];
#pragma unroll
  for (int o = 0; o < 32; ++o) acc[o] = 0.0f;
  const float* wb = Ws + q * 32 * 64;
#pragma unroll 4
  for (int j = 0; j < 64; ++j) {
    float f = Fs[r * 65 + j];
#pragma unroll
    for (int o = 0; o < 32; ++o) acc[o] += f * wb[o * 64 + j];
  }
  if (q < 2) {
    float4* dst = (float4*)(g_F1 + (size_t)(k0 + r) * 64 + q * 32);
#pragma unroll
    for (int v = 0; v < 8; ++v)
      dst[v] = make_float4(acc[4 * v], acc[4 * v + 1], acc[4 * v + 2], acc[4 * v + 3]);
  } else {
    __nv_bfloat162* dst = (__nv_bfloat162*)(g_B + (size_t)(k0 + r) * NP + (q - 2) * 32);
#pragma unroll
    for (int v = 0; v < 16; ++v)
      dst[v] = __floats2bfloat162_rn(acc[2 * v], acc[2 * v + 1]);
  }
  for (int idx = tid; idx < 64 * 16; idx += 256) {
    int rr = idx >> 4, c = 64 + (idx & 15);
    g_B[(size_t)(k0 + rr) * NP + c] = __float2bfloat16((c == 64) ? 1.0f : 0.0f);
  }
}

// ---------------------------------------------------------------------------
// gemm: Cp[kh][128-row block] = adj(rows, k-half) @ g_B(k-half)
// 256 thr = 4m(32 rows) x 2n(40 cols). A: 2-deep register pipeline -> smem.
// B: 4-stage cp.async ring, wait_group 2.
// ---------------------------------------------------------------------------
__global__ __launch_bounds__(256, 2) void gemm_kernel(const float* __restrict__ adj) {
  __shared__ __nv_bfloat16 As[MT * SA];            // 10240 B, single stage
  __shared__ __nv_bfloat16 Bs[BSTG][B_STG_ELEM];   // 22528 B

  const int tid = threadIdx.x;
  const int warp = tid >> 5;
  const int lane = tid & 31;
  const int wm = warp >> 1;    // 0..3 -> 32-row slice
  const int wn = warp & 1;     // 0..1 -> 40-col half
  const int rowBlk = blockIdx.x >> 1;
  const int kh = blockIdx.x & 1;
  const int i0 = rowBlk * MT;
  const size_t kbase0 = (size_t)kh * KHALF;

  // A coords: 128x32 f32 = 1024 float4, 4/thread
  int ar[4], ac4[4];
#pragma unroll
  for (int j = 0; j < 4; ++j) {
    int idx = tid + 256 * j;
    ar[j] = idx >> 3;
    ac4[j] = idx & 7;
  }
  // B cp.async coords: 32 rows x 10 uint4 = 320
  const int br0 = tid / 10, bc0 = tid % 10;
  const int br1 = (tid + 256) / 10, bc1 = (tid + 256) % 10;
  const bool bok1 = tid < 64;
  const uint32_t bs_base = smem_u32(Bs);

  // ldmatrix lane addresses
  const uint32_t a_base = smem_u32(As);
  const uint32_t aAddr = a_base +
      (uint32_t)((wm * 32 + (lane & 15)) * SA + (lane >> 4) * 8) * 2;
  const int bRow = lane & 15;
  const int nOff = (lane >> 4) * 8;
  const uint32_t bAddrP0 = bs_base + (uint32_t)(bRow * SB + wn * 40 + nOff) * 2;
  const uint32_t bAddrP1 = bAddrP0 + 16 * 2;
  const uint32_t bAddr4 = bs_base + (uint32_t)(bRow * SB + 32 + nOff) * 2;

  auto issueB = [&](int ch) {
    const size_t kb = kbase0 + (size_t)ch * KC;
    const uint32_t dst = bs_base + (uint32_t)((ch & 3) * B_STG_ELEM * 2);
    cp16(dst + (uint32_t)(br0 * SB * 2 + bc0 * 16), g_B + (kb + br0) * NP + bc0 * 8);
    if (bok1)
      cp16(dst + (uint32_t)(br1 * SB * 2 + bc1 * 16), g_B + (kb + br1) * NP + bc1 * 8);
  };
  auto loadA = [&](int ch, float4* r) {
    const size_t kb = kbase0 + (size_t)ch * KC;
#pragma unroll
    for (int j = 0; j < 4; ++j)
      r[j] = *(const float4*)(adj + (size_t)(i0 + ar[j]) * NROWS + kb + ac4[j] * 4);
  };
  auto stsA = [&](const float4* r) {
#pragma unroll
    for (int j = 0; j < 4; ++j) {
      __nv_bfloat162 lo = __floats2bfloat162_rn(r[j].x, r[j].y);
      __nv_bfloat162 hi = __floats2bfloat162_rn(r[j].z, r[j].w);
      uint32_t* d = (uint32_t*)(As + ar[j] * SA + ac4[j] * 4);
      d[0] = *(uint32_t*)&lo;
      d[1] = *(uint32_t*)&hi;
    }
  };

  // prologue: A chunks 0,1 in regs; B chunks 0,1 in flight
  float4 rA[2][4];
  loadA(0, rA[0]);
  loadA(1, rA[1]);
  issueB(0); CP_COMMIT();
  issueB(1); CP_COMMIT();

  float acc[2][5][4];
#pragma unroll
  for (int m = 0; m < 2; ++m)
#pragma unroll
    for (int n = 0; n < 5; ++n)
#pragma unroll
      for (int v = 0; v < 4; ++v) acc[m][n][v] = 0.0f;

  for (int ch = 0; ch < NCHUNK; ++ch) {
    stsA(rA[ch & 1]);                         // commit chunk ch to smem
    if (ch + 2 < NCHUNK) {
      loadA(ch + 2, rA[ch & 1]);              // refill: 2 chunks of latency cover
      issueB(ch + 2);
    }
    CP_COMMIT();
    CP_WAIT2();                               // B(ch) landed
    __syncthreads();                          // visibility of STS + cp.async

    const uint32_t bOff = (uint32_t)((ch & 3) * B_STG_ELEM * 2);
#pragma unroll
    for (int ks = 0; ks < 2; ++ks) {
      uint32_t a0[4], a1[4], b01[4], b23[4], b4[2];
      const uint32_t ko = (uint32_t)(ks * 16 * 2);
      const uint32_t bo = bOff + (uint32_t)(ks * 16 * SB * 2);
      ldsm_x4(a0, aAddr + ko);
      ldsm_x4(a1, aAddr + (uint32_t)(16 * SA * 2) + ko);
      ldsm_x4t(b01, bAddrP0 + bo);
      ldsm_x4t(b23, bAddrP1 + bo);
      if (wn == 0) {
        ldsm_x2t(b4, bAddr4 + bo);
        mma_bf16(acc[0][4], a0, b4[0], b4[1]);
        mma_bf16(acc[1][4], a1, b4[0], b4[1]);
      }
      mma_bf16(acc[0][0], a0, b01[0], b01[1]);
      mma_bf16(acc[0][1], a0, b01[2], b01[3]);
      mma_bf16(acc[0][2], a0, b23[0], b23[1]);
      mma_bf16(acc[0][3], a0, b23[2], b23[3]);
      mma_bf16(acc[1][0], a1, b01[0], b01[1]);
      mma_bf16(acc[1][1], a1, b01[2], b01[3]);
      mma_bf16(acc[1][2], a1, b23[0], b23[1]);
      mma_bf16(acc[1][3], a1, b23[2], b23[3]);
    }
    __syncthreads();                          // As reuse guard
  }

  // store partial C
  float* Cp = g_Cp[kh];
  const int ntMax = (wn == 0) ? 5 : 4;
#pragma unroll
  for (int m = 0; m < 2; ++m) {
    const int r0 = i0 + wm * 32 + 16 * m + (lane >> 2);
#pragma unroll
    for (int nt = 0; nt < 5; ++nt) {
      if (nt >= ntMax) break;
      const int col = wn * 40 + nt * 8 + 2 * (lane & 3);
      *(float2*)(Cp + (size_t)r0 * NC + col) = make_float2(acc[m][nt][0], acc[m][nt][1]);
      *(float2*)(Cp + (size_t)(r0 + 8) * NC + col) = make_float2(acc[m][nt][2], acc[m][nt][3]);
    }
  }
}

// ---------------------------------------------------------------------------
// epi: out = F1 + (C0 + C1)[:, :64] / (C0[:,64] + C1[:,64] + 1)
// ---------------------------------------------------------------------------
__global__ __launch_bounds__(256, 4) void epi_kernel(float* __restrict__ out) {
  __shared__ float inv[32];
  const int tid = threadIdx.x;
  const int r0 = blockIdx.x * 32;

  if (tid < 32)
    inv[tid] = 1.0f / (g_Cp[0][(size_t)(r0 + tid) * NC + 64] +
                       g_Cp[1][(size_t)(r0 + tid) * NC + 64] + 1.0f);
  __syncthreads();

  const int r = tid >> 3;
  const int c = (tid & 7) * 8;
  const int row = r0 + r;
  const float iv = inv[r];
  const size_t cb = (size_t)row * NC + c;
  const size_t fb = (size_t)row * 64 + c;
#pragma unroll
  for (int h = 0; h < 2; ++h) {
    float4 c0 = *(const float4*)(g_Cp[0] + cb + 4 * h);
    float4 c1 = *(const float4*)(g_Cp[1] + cb + 4 * h);
    float4 f = *(const float4*)(g_F1 + fb + 4 * h);
    *(float4*)(out + fb + 4 * h) =
        make_float4(f.x + (c0.x + c1.x) * iv, f.y + (c0.y + c1.y) * iv,
                    f.z + (c0.z + c1.z) * iv, f.w + (c0.w + c1.w) * iv);
  }
}

// ---------------------------------------------------------------------------
extern "C" void kernel_launch(void* const* d_in, const int* in_sizes, int n_in,
                              void* d_out, int out_size) {
  const float* feat = nullptr;
  const float* adj = nullptr;
  const float* W = nullptr;
  for (int i = 0; i < n_in; ++i) {
    if (in_sizes[i] == NROWS * FIN)          feat = (const float*)d_in[i];
    else if (in_sizes[i] == FOUT * 2 * FIN)  W    = (const float*)d_in[i];
    else                                     adj  = (const float*)d_in[i];
  }

  cudaFuncSetAttribute(prep_kernel, cudaFuncAttributeMaxDynamicSharedMemorySize, PREP_SMEM);
  probe_kernel<<<1, 32>>>();                              // idx 0
  prep_kernel<<<NROWS / 64, 256, PREP_SMEM>>>(feat, W);   // idx 1
  probe_kernel<<<1, 32>>>();                              // idx 2
  gemm_kernel<<<2 * (NROWS / MT), 256>>>(adj);            // idx 3  <- ncu capture slot
  epi_kernel<<<NROWS / 32, 256>>>((float*)d_out);         // idx 4
}

// round 7
// speedup vs baseline: 1.7031x; 1.7031x over previous
#include <cuda_runtime.h>
#include <cuda_bf16.h>
#include <cstdint>

#define NROWS 16384
#define FIN 64
#define FOUT 64
#define NP 80             // g_B row: 0..63 = feat@W2^T, 64 = ones, 65..79 = 0
#define NC 72             // stored C cols
#define MT 128            // M rows per CTA
#define KC 32             // K per chunk
#define KHALF (NROWS / 2)
#define NCHUNK (KHALF / KC)     // 256
#define SA 40             // A smem stride (bf16), conflict-free LDSM
#define SB 88             // B smem stride (bf16), conflict-free LDSM
#define BSTG 4
#define B_STG_ELEM (KC * SB)    // 2816 bf16 = 5632 B
#define PREP_SMEM ((64 * 65 + 128 * 64) * 4)

__device__ __align__(256) __nv_bfloat16 g_B[NROWS * NP];
__device__ __align__(256) float g_F1[NROWS * FOUT];
__device__ __align__(256) float g_Cp[2][NROWS * NC];

__device__ __forceinline__ uint32_t smem_u32(const void* p) {
  uint32_t a;
  asm("{ .reg .u64 t; cvta.to.shared.u64 t, %1; cvt.u32.u64 %0, t; }" : "=r"(a) : "l"(p));
  return a;
}
__device__ __forceinline__ void cp16(uint32_t dst, const void* src) {
  asm volatile("cp.async.cg.shared.global [%0], [%1], 16;" :: "r"(dst), "l"(src));
}
#define CP_COMMIT() asm volatile("cp.async.commit_group;" ::: "memory")
#define CP_WAIT2()  asm volatile("cp.async.wait_group 2;" ::: "memory")
__device__ __forceinline__ void ldsm_x4(uint32_t* r, uint32_t a) {
  asm volatile("ldmatrix.sync.aligned.m8n8.x4.shared.b16 {%0,%1,%2,%3}, [%4];"
               : "=r"(r[0]), "=r"(r[1]), "=r"(r[2]), "=r"(r[3]) : "r"(a));
}
__device__ __forceinline__ void ldsm_x4t(uint32_t* r, uint32_t a) {
  asm volatile("ldmatrix.sync.aligned.m8n8.x4.trans.shared.b16 {%0,%1,%2,%3}, [%4];"
               : "=r"(r[0]), "=r"(r[1]), "=r"(r[2]), "=r"(r[3]) : "r"(a));
}
__device__ __forceinline__ void ldsm_x2t(uint32_t* r, uint32_t a) {
  asm volatile("ldmatrix.sync.aligned.m8n8.x2.trans.shared.b16 {%0,%1}, [%2];"
               : "=r"(r[0]), "=r"(r[1]) : "r"(a));
}
__device__ __forceinline__ void mma_bf16(float* c, const uint32_t* a, uint32_t b0, uint32_t b1) {
  asm volatile(
      "mma.sync.aligned.m16n8k16.row.col.f32.bf16.bf16.f32 "
      "{%0,%1,%2,%3}, {%4,%5,%6,%7}, {%8,%9}, {%0,%1,%2,%3};\n"
      : "+f"(c[0]), "+f"(c[1]), "+f"(c[2]), "+f"(c[3])
      : "r"(a[0]), "r"(a[1]), "r"(a[2]), "r"(a[3]), "r"(b0), "r"(b1));
}

// ---------------------------------------------------------------------------
__global__ void probe_kernel() {}   // alignment: gemm = overall launch idx 3

// ---------------------------------------------------------------------------
// prep: g_F1 = feat@W1^T (f32); g_B[k][0..63] = feat@W2^T (bf16); 64=1; pad=0
// ---------------------------------------------------------------------------
__global__ __launch_bounds__(256, 2) void prep_kernel(const float* __restrict__ feat,
                                                      const float* __restrict__ W) {
  extern __shared__ float sm[];
  float* Fs = sm;             // [64][65]
  float* Ws = sm + 64 * 65;   // [128][64]
  const int tid = threadIdx.x;
  const int k0 = blockIdx.x * 64;

  for (int idx = tid; idx < 64 * 64; idx += 256) {
    int r = idx >> 6, j = idx & 63;
    Fs[r * 65 + j] = feat[(size_t)(k0 + r) * 64 + j];
  }
  for (int idx = tid; idx < 64 * 128; idx += 256) {
    int o = idx >> 7, j = idx & 127;
    Ws[((j < 64) ? o : 64 + o) * 64 + (j & 63)] = W[idx];
  }
  __syncthreads();

  const int r = tid & 63;
  const int q = tid >> 6;
  float acc[32];
#pragma unroll
  for (int o = 0; o < 32; ++o) acc[o] = 0.0f;
  const float* wb = Ws + q * 32 * 64;
#pragma unroll 4
  for (int j = 0; j < 64; ++j) {
    float f = Fs[r * 65 + j];
#pragma unroll
    for (int o = 0; o < 32; ++o) acc[o] += f * wb[o * 64 + j];
  }
  if (q < 2) {
    float4* dst = (float4*)(g_F1 + (size_t)(k0 + r) * 64 + q * 32);
#pragma unroll
    for (int v = 0; v < 8; ++v)
      dst[v] = make_float4(acc[4 * v], acc[4 * v + 1], acc[4 * v + 2], acc[4 * v + 3]);
  } else {
    __nv_bfloat162* dst = (__nv_bfloat162*)(g_B + (size_t)(k0 + r) * NP + (q - 2) * 32);
#pragma unroll
    for (int v = 0; v < 16; ++v)
      dst[v] = __floats2bfloat162_rn(acc[2 * v], acc[2 * v + 1]);
  }
  for (int idx = tid; idx < 64 * 16; idx += 256) {
    int rr = idx >> 4, c = 64 + (idx & 15);
    g_B[(size_t)(k0 + rr) * NP + c] = __float2bfloat16((c == 64) ? 1.0f : 0.0f);
  }
}

// ---------------------------------------------------------------------------
// gemm: Cp[kh][128-row block] = adj(rows, k-half) @ g_B(k-half)
// 256 thr = 4m(32 rows) x 2n(40 cols). A: asm-pinned depth-2 register pipeline.
// B: 4-stage cp.async ring.
// ---------------------------------------------------------------------------
__global__ __launch_bounds__(256, 2) void gemm_kernel(const float* __restrict__ adj) {
  __shared__ __nv_bfloat16 As[MT * SA];            // 10240 B
  __shared__ __nv_bfloat16 Bs[BSTG][B_STG_ELEM];   // 22528 B

  const int tid = threadIdx.x;
  const int warp = tid >> 5;
  const int lane = tid & 31;
  const int wm = warp >> 1;
  const int wn = warp & 1;
  const int rowBlk = blockIdx.x >> 1;
  const int kh = blockIdx.x & 1;
  const int i0 = rowBlk * MT;
  const size_t kbase0 = (size_t)kh * KHALF;

  // A coords: 128x32 f32 = 1024 float4, 4/thread
  int ar[4], ac4[4];
#pragma unroll
  for (int j = 0; j < 4; ++j) {
    int idx = tid + 256 * j;
    ar[j] = idx >> 3;
    ac4[j] = idx & 7;
  }
  // pinned A source pointers (advance KC floats per loadA call)
  const float* ap[4];
#pragma unroll
  for (int j = 0; j < 4; ++j)
    ap[j] = adj + (size_t)(i0 + ar[j]) * NROWS + kbase0 + ac4[j] * 4;
  // A smem store byte addresses
  const uint32_t a_base = smem_u32(As);
  uint32_t aSt[4];
#pragma unroll
  for (int j = 0; j < 4; ++j)
    aSt[j] = a_base + (uint32_t)(ar[j] * SA + ac4[j] * 4) * 2;

  // B cp.async coords: 32 rows x 10 uint4 = 320
  const int br0 = tid / 10, bc0 = tid % 10;
  const int br1 = (tid + 256) / 10, bc1 = (tid + 256) % 10;
  const bool bok1 = tid < 64;
  const uint32_t bs_base = smem_u32(Bs);
  const __nv_bfloat16* bsrc0 = g_B + (kbase0 + br0) * NP + bc0 * 8;
  const __nv_bfloat16* bsrc1 = g_B + (kbase0 + br1) * NP + bc1 * 8;
  const uint32_t bd0 = (uint32_t)(br0 * SB * 2 + bc0 * 16);
  const uint32_t bd1 = (uint32_t)(br1 * SB * 2 + bc1 * 16);

  // ldmatrix lane addresses
  const uint32_t aAddr = a_base +
      (uint32_t)((wm * 32 + (lane & 15)) * SA + (lane >> 4) * 8) * 2;
  const int bRow = lane & 15;
  const int nOff = (lane >> 4) * 8;
  const uint32_t bAddrP0 = bs_base + (uint32_t)(bRow * SB + wn * 40 + nOff) * 2;
  const uint32_t bAddrP1 = bAddrP0 + 16 * 2;
  const uint32_t bAddr4 = bs_base + (uint32_t)(bRow * SB + 32 + nOff) * 2;

  auto loadA = [&](float4* r) {
#pragma unroll
    for (int j = 0; j < 4; ++j) {
      asm volatile("ld.global.nc.L2::128B.v4.f32 {%0,%1,%2,%3}, [%4];"
                   : "=f"(r[j].x), "=f"(r[j].y), "=f"(r[j].z), "=f"(r[j].w)
                   : "l"(ap[j]));
      ap[j] += KC;
    }
  };
  auto stsA = [&](const float4* r) {
#pragma unroll
    for (int j = 0; j < 4; ++j) {
      __nv_bfloat162 lo = __floats2bfloat162_rn(r[j].x, r[j].y);
      __nv_bfloat162 hi = __floats2bfloat162_rn(r[j].z, r[j].w);
      asm volatile("st.shared.v2.b32 [%0], {%1,%2};"
                   :: "r"(aSt[j]), "r"(*(uint32_t*)&lo), "r"(*(uint32_t*)&hi)
                   : "memory");
    }
  };
  auto issueB = [&](int ch) {
    const uint32_t dst = bs_base + (uint32_t)((ch & 3) * B_STG_ELEM * 2);
    const size_t off = (size_t)ch * KC * NP;
    cp16(dst + bd0, bsrc0 + off);
    if (bok1) cp16(dst + bd1, bsrc1 + off);
  };

  // prologue: A chunks 0,1 pinned-loaded into regs; B chunks 0,1 in flight
  float4 rA[2][4];
  loadA(rA[0]);
  loadA(rA[1]);
  issueB(0); CP_COMMIT();
  issueB(1); CP_COMMIT();

  float acc[2][5][4];
#pragma unroll
  for (int m = 0; m < 2; ++m)
#pragma unroll
    for (int n = 0; n < 5; ++n)
#pragma unroll
      for (int v = 0; v < 4; ++v) acc[m][n][v] = 0.0f;

  for (int ch = 0; ch < NCHUNK; ++ch) {
    stsA(rA[ch & 1]);                // commit chunk ch (loaded 2 iters ago)
    if (ch + 2 < NCHUNK) {
      loadA(rA[ch & 1]);             // pinned LDG for chunk ch+2
      issueB(ch + 2);
    }
    CP_COMMIT();
    CP_WAIT2();                      // B(ch) landed
    __syncthreads();

    const uint32_t bOff = (uint32_t)((ch & 3) * B_STG_ELEM * 2);
#pragma unroll
    for (int ks = 0; ks < 2; ++ks) {
      uint32_t a0[4], a1[4], b01[4], b23[4], b4[2];
      const uint32_t ko = (uint32_t)(ks * 16 * 2);
      const uint32_t bo = bOff + (uint32_t)(ks * 16 * SB * 2);
      ldsm_x4(a0, aAddr + ko);
      ldsm_x4(a1, aAddr + (uint32_t)(16 * SA * 2) + ko);
      ldsm_x4t(b01, bAddrP0 + bo);
      ldsm_x4t(b23, bAddrP1 + bo);
      if (wn == 0) {
        ldsm_x2t(b4, bAddr4 + bo);
        mma_bf16(acc[0][4], a0, b4[0], b4[1]);
        mma_bf16(acc[1][4], a1, b4[0], b4[1]);
      }
      mma_bf16(acc[0][0], a0, b01[0], b01[1]);
      mma_bf16(acc[0][1], a0, b01[2], b01[3]);
      mma_bf16(acc[0][2], a0, b23[0], b23[1]);
      mma_bf16(acc[0][3], a0, b23[2], b23[3]);
      mma_bf16(acc[1][0], a1, b01[0], b01[1]);
      mma_bf16(acc[1][1], a1, b01[2], b01[3]);
      mma_bf16(acc[1][2], a1, b23[0], b23[1]);
      mma_bf16(acc[1][3], a1, b23[2], b23[3]);
    }
    __syncthreads();                 // As reuse guard
  }

  // store partial C
  float* Cp = g_Cp[kh];
  const int ntMax = (wn == 0) ? 5 : 4;
#pragma unroll
  for (int m = 0; m < 2; ++m) {
    const int r0 = i0 + wm * 32 + 16 * m + (lane >> 2);
#pragma unroll
    for (int nt = 0; nt < 5; ++nt) {
      if (nt >= ntMax) break;
      const int col = wn * 40 + nt * 8 + 2 * (lane & 3);
      *(float2*)(Cp + (size_t)r0 * NC + col) = make_float2(acc[m][nt][0], acc[m][nt][1]);
      *(float2*)(Cp + (size_t)(r0 + 8) * NC + col) = make_float2(acc[m][nt][2], acc[m][nt][3]);
    }
  }
}

// ---------------------------------------------------------------------------
// epi: out = F1 + (C0 + C1)[:, :64] / (C0[:,64] + C1[:,64] + 1)
// ---------------------------------------------------------------------------
__global__ __launch_bounds__(256, 4) void epi_kernel(float* __restrict__ out) {
  __shared__ float inv[32];
  const int tid = threadIdx.x;
  const int r0 = blockIdx.x * 32;

  if (tid < 32)
    inv[tid] = 1.0f / (g_Cp[0][(size_t)(r0 + tid) * NC + 64] +
                       g_Cp[1][(size_t)(r0 + tid) * NC + 64] + 1.0f);
  __syncthreads();

  const int r = tid >> 3;
  const int c = (tid & 7) * 8;
  const int row = r0 + r;
  const float iv = inv[r];
  const size_t cb = (size_t)row * NC + c;
  const size_t fb = (size_t)row * 64 + c;
#pragma unroll
  for (int h = 0; h < 2; ++h) {
    float4 c0 = *(const float4*)(g_Cp[0] + cb + 4 * h);
    float4 c1 = *(const float4*)(g_Cp[1] + cb + 4 * h);
    float4 f = *(const float4*)(g_F1 + fb + 4 * h);
    *(float4*)(out + fb + 4 * h) =
        make_float4(f.x + (c0.x + c1.x) * iv, f.y + (c0.y + c1.y) * iv,
                    f.z + (c0.z + c1.z) * iv, f.w + (c0.w + c1.w) * iv);
  }
}

// ---------------------------------------------------------------------------
extern "C" void kernel_launch(void* const* d_in, const int* in_sizes, int n_in,
                              void* d_out, int out_size) {
  const float* feat = nullptr;
  const float* adj = nullptr;
  const float* W = nullptr;
  for (int i = 0; i < n_in; ++i) {
    if (in_sizes[i] == NROWS * FIN)          feat = (const float*)d_in[i];
    else if (in_sizes[i] == FOUT * 2 * FIN)  W    = (const float*)d_in[i];
    else                                     adj  = (const float*)d_in[i];
  }

  cudaFuncSetAttribute(prep_kernel, cudaFuncAttributeMaxDynamicSharedMemorySize, PREP_SMEM);
  probe_kernel<<<1, 32>>>();                              // idx 0
  prep_kernel<<<NROWS / 64, 256, PREP_SMEM>>>(feat, W);   // idx 1
  probe_kernel<<<1, 32>>>();                              // idx 2
  gemm_kernel<<<2 * (NROWS / MT), 256>>>(adj);            // idx 3  <- ncu slot
  epi_kernel<<<NROWS / 32, 256>>>((float*)d_out);         // idx 4
}

// round 8
// speedup vs baseline: 2.0367x; 1.1959x over previous
#include <cuda_runtime.h>
#include <cuda_bf16.h>
#include <cstdint>

#define NROWS 16384
#define FIN 64
#define FOUT 64
#define NP 80             // g_B row: 0..63 = feat@W2^T, 64 = ones, 65..79 = 0
#define NC 72             // stored C cols
#define MT 128            // M rows per CTA
#define KC 64             // K per chunk
#define KHALF (NROWS / 2)
#define NCHUNK (KHALF / KC)     // 128
#define SA 72             // A smem stride (bf16): 144B/row -> conflict-free LDSM
#define SB 88             // B smem stride (bf16): 176B/row -> conflict-free LDSM
#define ASTG 2
#define BSTG 3
#define A_STG_BYTES (MT * SA * 2)     // 18432
#define B_STG_BYTES (KC * SB * 2)     // 11264
#define GEMM_SMEM (ASTG * A_STG_BYTES + BSTG * B_STG_BYTES)   // 70656
#define PREP_SMEM ((64 * 65 + 128 * 64) * 4)

__device__ __align__(256) __nv_bfloat16 g_B[NROWS * NP];
__device__ __align__(256) float g_F1[NROWS * FOUT];
__device__ __align__(256) float g_Cp[2][NROWS * NC];

__device__ __forceinline__ uint32_t smem_u32(const void* p) {
  uint32_t a;
  asm("{ .reg .u64 t; cvta.to.shared.u64 t, %1; cvt.u32.u64 %0, t; }" : "=r"(a) : "l"(p));
  return a;
}
__device__ __forceinline__ void cp16(uint32_t dst, const void* src) {
  asm volatile("cp.async.cg.shared.global [%0], [%1], 16;" :: "r"(dst), "l"(src));
}
#define CP_COMMIT() asm volatile("cp.async.commit_group;" ::: "memory")
#define CP_WAIT1()  asm volatile("cp.async.wait_group 1;" ::: "memory")
__device__ __forceinline__ void ldsm_x4(uint32_t* r, uint32_t a) {
  asm volatile("ldmatrix.sync.aligned.m8n8.x4.shared.b16 {%0,%1,%2,%3}, [%4];"
               : "=r"(r[0]), "=r"(r[1]), "=r"(r[2]), "=r"(r[3]) : "r"(a));
}
__device__ __forceinline__ void ldsm_x4t(uint32_t* r, uint32_t a) {
  asm volatile("ldmatrix.sync.aligned.m8n8.x4.trans.shared.b16 {%0,%1,%2,%3}, [%4];"
               : "=r"(r[0]), "=r"(r[1]), "=r"(r[2]), "=r"(r[3]) : "r"(a));
}
__device__ __forceinline__ void ldsm_x2t(uint32_t* r, uint32_t a) {
  asm volatile("ldmatrix.sync.aligned.m8n8.x2.trans.shared.b16 {%0,%1}, [%2];"
               : "=r"(r[0]), "=r"(r[1]) : "r"(a));
}
__device__ __forceinline__ void mma_bf16(float* c, const uint32_t* a, uint32_t b0, uint32_t b1) {
  asm volatile(
      "mma.sync.aligned.m16n8k16.row.col.f32.bf16.bf16.f32 "
      "{%0,%1,%2,%3}, {%4,%5,%6,%7}, {%8,%9}, {%0,%1,%2,%3};\n"
      : "+f"(c[0]), "+f"(c[1]), "+f"(c[2]), "+f"(c[3])
      : "r"(a[0]), "r"(a[1]), "r"(a[2]), "r"(a[3]), "r"(b0), "r"(b1));
}

// ---------------------------------------------------------------------------
__global__ void probe_kernel() {}   // alignment: gemm = overall launch idx 3

// ---------------------------------------------------------------------------
// prep: g_F1 = feat@W1^T (f32); g_B[k][0..63] = feat@W2^T (bf16); 64=1; pad=0
// ---------------------------------------------------------------------------
__global__ __launch_bounds__(256, 2) void prep_kernel(const float* __restrict__ feat,
                                                      const float* __restrict__ W) {
  extern __shared__ float sm[];
  float* Fs = sm;             // [64][65]
  float* Ws = sm + 64 * 65;   // [128][64]
  const int tid = threadIdx.x;
  const int k0 = blockIdx.x * 64;

  for (int idx = tid; idx < 64 * 64; idx += 256) {
    int r = idx >> 6, j = idx & 63;
    Fs[r * 65 + j] = feat[(size_t)(k0 + r) * 64 + j];
  }
  for (int idx = tid; idx < 64 * 128; idx += 256) {
    int o = idx >> 7, j = idx & 127;
    Ws[((j < 64) ? o : 64 + o) * 64 + (j & 63)] = W[idx];
  }
  __syncthreads();

  const int r = tid & 63;
  const int q = tid >> 6;
  float acc[32];
#pragma unroll
  for (int o = 0; o < 32; ++o) acc[o] = 0.0f;
  const float* wb = Ws + q * 32 * 64;
#pragma unroll 4
  for (int j = 0; j < 64; ++j) {
    float f = Fs[r * 65 + j];
#pragma unroll
    for (int o = 0; o < 32; ++o) acc[o] += f * wb[o * 64 + j];
  }
  if (q < 2) {
    float4* dst = (float4*)(g_F1 + (size_t)(k0 + r) * 64 + q * 32);
#pragma unroll
    for (int v = 0; v < 8; ++v)
      dst[v] = make_float4(acc[4 * v], acc[4 * v + 1], acc[4 * v + 2], acc[4 * v + 3]);
  } else {
    __nv_bfloat162* dst = (__nv_bfloat162*)(g_B + (size_t)(k0 + r) * NP + (q - 2) * 32);
#pragma unroll
    for (int v = 0; v < 16; ++v)
      dst[v] = __floats2bfloat162_rn(acc[2 * v], acc[2 * v + 1]);
  }
  for (int idx = tid; idx < 64 * 16; idx += 256) {
    int rr = idx >> 4, c = 64 + (idx & 15);
    g_B[(size_t)(k0 + rr) * NP + c] = __float2bfloat16((c == 64) ? 1.0f : 0.0f);
  }
}

// ---------------------------------------------------------------------------
// gemm: Cp[kh][128-row block] = adj(rows, k-half) @ g_B(k-half)
// KC=64, single __syncthreads per chunk, 2-stage A smem, 3-stage B cp.async.
// A: asm-pinned LDG (8x128b/thread) -> regs -> bf16 STS one iter later.
// ---------------------------------------------------------------------------
__global__ __launch_bounds__(256, 2) void gemm_kernel(const float* __restrict__ adj) {
  extern __shared__ __align__(128) char smem[];
  __nv_bfloat16* As = (__nv_bfloat16*)smem;                          // 2 stages
  __nv_bfloat16* Bs = (__nv_bfloat16*)(smem + ASTG * A_STG_BYTES);   // 3 stages

  const int tid = threadIdx.x;
  const int warp = tid >> 5;
  const int lane = tid & 31;
  const int wm = warp >> 1;
  const int wn = warp & 1;
  const int rowBlk = blockIdx.x >> 1;
  const int kh = blockIdx.x & 1;
  const int i0 = rowBlk * MT;
  const size_t kbase0 = (size_t)kh * KHALF;

  // A coords: 128 rows x 16 float4/row; thread j-th load: row r0+16j, col c4
  const int r0 = tid >> 4;
  const int c4 = tid & 15;
  const float* ap0 = adj + (size_t)(i0 + r0) * NROWS + kbase0 + c4 * 4;
  const uint32_t a_base = smem_u32(As);
  const uint32_t aSt0 = a_base + (uint32_t)(r0 * SA + c4 * 4) * 2;

  // B cp.async coords: 64 rows x 10 uint4 = 640
  const int br0 = tid / 10, bc0 = tid % 10;
  const int br1 = (tid + 256) / 10, bc1 = (tid + 256) % 10;
  const int br2 = (tid + 512) / 10, bc2 = (tid + 512) % 10;
  const bool bok2 = tid < 128;
  const uint32_t bs_base = smem_u32(Bs);
  const __nv_bfloat16* bsrc0 = g_B + (kbase0 + br0) * NP + bc0 * 8;
  const __nv_bfloat16* bsrc1 = g_B + (kbase0 + br1) * NP + bc1 * 8;
  const __nv_bfloat16* bsrc2 = g_B + (kbase0 + br2) * NP + bc2 * 8;
  const uint32_t bd0 = (uint32_t)(br0 * SB * 2 + bc0 * 16);
  const uint32_t bd1 = (uint32_t)(br1 * SB * 2 + bc1 * 16);
  const uint32_t bd2 = (uint32_t)(br2 * SB * 2 + bc2 * 16);

  // ldmatrix lane addresses
  const uint32_t aAddr = a_base +
      (uint32_t)((wm * 32 + (lane & 15)) * SA + (lane >> 4) * 8) * 2;
  const int bRow = lane & 15;
  const int nOff = (lane >> 4) * 8;
  const uint32_t bAddrP0 = bs_base + (uint32_t)(bRow * SB + wn * 40 + nOff) * 2;
  const uint32_t bAddrP1 = bAddrP0 + 16 * 2;
  const uint32_t bAddr4 = bs_base + (uint32_t)(bRow * SB + 32 + nOff) * 2;

  float4 rA[8];
  const float* apc = ap0;
  auto loadA = [&]() {
#pragma unroll
    for (int j = 0; j < 8; ++j) {
      asm volatile("ld.global.nc.L2::128B.v4.f32 {%0,%1,%2,%3}, [%4];"
                   : "=f"(rA[j].x), "=f"(rA[j].y), "=f"(rA[j].z), "=f"(rA[j].w)
                   : "l"(apc + (size_t)j * 16 * NROWS));
    }
    apc += KC;
  };
  auto stsA = [&](int stg) {
    const uint32_t base = aSt0 + (uint32_t)(stg * A_STG_BYTES);
#pragma unroll
    for (int j = 0; j < 8; ++j) {
      __nv_bfloat162 lo = __floats2bfloat162_rn(rA[j].x, rA[j].y);
      __nv_bfloat162 hi = __floats2bfloat162_rn(rA[j].z, rA[j].w);
      asm volatile("st.shared.v2.b32 [%0], {%1,%2};"
                   :: "r"(base + (uint32_t)(j * 16 * SA * 2)),
                      "r"(*(uint32_t*)&lo), "r"(*(uint32_t*)&hi)
                   : "memory");
    }
  };
  auto issueB = [&](int ch, int stg) {
    const uint32_t dst = bs_base + (uint32_t)(stg * B_STG_BYTES);
    const size_t off = (size_t)ch * KC * NP;
    cp16(dst + bd0, bsrc0 + off);
    cp16(dst + bd1, bsrc1 + off);
    if (bok2) cp16(dst + bd2, bsrc2 + off);
  };

  // prologue: A0 -> regs -> stage0; A1 -> regs. B0,B1 in flight.
  loadA();            // chunk 0
  stsA(0);
  loadA();            // chunk 1
  issueB(0, 0); CP_COMMIT();
  issueB(1, 1); CP_COMMIT();

  float acc[2][5][4];
#pragma unroll
  for (int m = 0; m < 2; ++m)
#pragma unroll
    for (int n = 0; n < 5; ++n)
#pragma unroll
      for (int v = 0; v < 4; ++v) acc[m][n][v] = 0.0f;

  int bW = 2;   // next B write stage
  int bR = 0;   // B read stage for chunk ch
  for (int ch = 0; ch < NCHUNK; ++ch) {
    CP_WAIT1();                      // B(ch) landed
    __syncthreads();                 // A stage (ch&1) + B stage bR visible

    const uint32_t aOff = (uint32_t)((ch & 1) * A_STG_BYTES);
    const uint32_t bOff = (uint32_t)(bR * B_STG_BYTES);
#pragma unroll
    for (int ks = 0; ks < 4; ++ks) {
      uint32_t a0[4], a1[4], b01[4], b23[4], b4[2];
      const uint32_t ko = (uint32_t)(ks * 16 * 2);
      const uint32_t bo = bOff + (uint32_t)(ks * 16 * SB * 2);
      ldsm_x4(a0, aAddr + aOff + ko);
      ldsm_x4(a1, aAddr + aOff + (uint32_t)(16 * SA * 2) + ko);
      ldsm_x4t(b01, bAddrP0 + bo);
      ldsm_x4t(b23, bAddrP1 + bo);
      if (wn == 0) {
        ldsm_x2t(b4, bAddr4 + bo);
        mma_bf16(acc[0][4], a0, b4[0], b4[1]);
        mma_bf16(acc[1][4], a1, b4[0], b4[1]);
      }
      mma_bf16(acc[0][0], a0, b01[0], b01[1]);
      mma_bf16(acc[0][1], a0, b01[2], b01[3]);
      mma_bf16(acc[0][2], a0, b23[0], b23[1]);
      mma_bf16(acc[0][3], a0, b23[2], b23[3]);
      mma_bf16(acc[1][0], a1, b01[0], b01[1]);
      mma_bf16(acc[1][1], a1, b01[2], b01[3]);
      mma_bf16(acc[1][2], a1, b23[0], b23[1]);
      mma_bf16(acc[1][3], a1, b23[2], b23[3]);
    }

    // post-compute: commit chunk ch+1 to the other A stage, refill regs, feed B
    if (ch + 1 < NCHUNK) stsA((ch + 1) & 1);
    if (ch + 2 < NCHUNK) {
      loadA();                       // pinned LDG for chunk ch+2
      issueB(ch + 2, bW);
      if (++bW == BSTG) bW = 0;
    }
    CP_COMMIT();
    if (++bR == BSTG) bR = 0;
  }

  // store partial C
  float* Cp = g_Cp[kh];
  const int ntMax = (wn == 0) ? 5 : 4;
#pragma unroll
  for (int m = 0; m < 2; ++m) {
    const int rr = i0 + wm * 32 + 16 * m + (lane >> 2);
#pragma unroll
    for (int nt = 0; nt < 5; ++nt) {
      if (nt >= ntMax) break;
      const int col = wn * 40 + nt * 8 + 2 * (lane & 3);
      *(float2*)(Cp + (size_t)rr * NC + col) = make_float2(acc[m][nt][0], acc[m][nt][1]);
      *(float2*)(Cp + (size_t)(rr + 8) * NC + col) = make_float2(acc[m][nt][2], acc[m][nt][3]);
    }
  }
}

// ---------------------------------------------------------------------------
// epi: out = F1 + (C0 + C1)[:, :64] / (C0[:,64] + C1[:,64] + 1)
// ---------------------------------------------------------------------------
__global__ __launch_bounds__(256, 4) void epi_kernel(float* __restrict__ out) {
  __shared__ float inv[32];
  const int tid = threadIdx.x;
  const int r0 = blockIdx.x * 32;

  if (tid < 32)
    inv[tid] = 1.0f / (g_Cp[0][(size_t)(r0 + tid) * NC + 64] +
                       g_Cp[1][(size_t)(r0 + tid) * NC + 64] + 1.0f);
  __syncthreads();

  const int r = tid >> 3;
  const int c = (tid & 7) * 8;
  const int row = r0 + r;
  const float iv = inv[r];
  const size_t cb = (size_t)row * NC + c;
  const size_t fb = (size_t)row * 64 + c;
#pragma unroll
  for (int h = 0; h < 2; ++h) {
    float4 c0 = *(const float4*)(g_Cp[0] + cb + 4 * h);
    float4 c1 = *(const float4*)(g_Cp[1] + cb + 4 * h);
    float4 f = *(const float4*)(g_F1 + fb + 4 * h);
    *(float4*)(out + fb + 4 * h) =
        make_float4(f.x + (c0.x + c1.x) * iv, f.y + (c0.y + c1.y) * iv,
                    f.z + (c0.z + c1.z) * iv, f.w + (c0.w + c1.w) * iv);
  }
}

// ---------------------------------------------------------------------------
extern "C" void kernel_launch(void* const* d_in, const int* in_sizes, int n_in,
                              void* d_out, int out_size) {
  const float* feat = nullptr;
  const float* adj = nullptr;
  const float* W = nullptr;
  for (int i = 0; i < n_in; ++i) {
    if (in_sizes[i] == NROWS * FIN)          feat = (const float*)d_in[i];
    else if (in_sizes[i] == FOUT * 2 * FIN)  W    = (const float*)d_in[i];
    else                                     adj  = (const float*)d_in[i];
  }

  cudaFuncSetAttribute(prep_kernel, cudaFuncAttributeMaxDynamicSharedMemorySize, PREP_SMEM);
  cudaFuncSetAttribute(gemm_kernel, cudaFuncAttributeMaxDynamicSharedMemorySize, GEMM_SMEM);

  probe_kernel<<<1, 32>>>();                               // idx 0
  prep_kernel<<<NROWS / 64, 256, PREP_SMEM>>>(feat, W);    // idx 1
  probe_kernel<<<1, 32>>>();                               // idx 2
  gemm_kernel<<<2 * (NROWS / MT), 256, GEMM_SMEM>>>(adj);  // idx 3  <- ncu slot
  epi_kernel<<<NROWS / 32, 256>>>((float*)d_out);          // idx 4
}